// round 2
// baseline (speedup 1.0000x reference)
#include <cuda_runtime.h>
#include <cuda_bf16.h>

// Problem constants (from reference): P=8, N=16, WS=32, H=W=512.
#define PP     8
#define NSLOT  16
#define WSZ    32
#define PITCH  36            // row pitch (multiple of 4 for float4 alignment)
#define HDIM   512
#define WDIM   512
#define MAXM   625           // (32-8+1)^2
#define NCHUNK 20            // ceil(625/32)
#define NPROD  224           // producer threads (warps 1..7)

__global__ __launch_bounds__(256, 1)
void patches_kernel(const float* __restrict__ g_re,
                    const float* __restrict__ g_im,
                    const int*   __restrict__ p_refx,
                    const int*   __restrict__ p_refy,
                    float*       __restrict__ out)
{
    __shared__ float wr[WSZ][PITCH];
    __shared__ float wi[WSZ][PITCH];
    __shared__ float ref_r[PP * PP];   // 16B-aligned, contiguous ref patch
    __shared__ float ref_i[PP * PP];
    __shared__ float dists[NCHUNK * 32];
    __shared__ int   chunk_cnt[NCHUNK];
    __shared__ int   sel[NSLOT];

    const int bc  = blockIdx.x;
    const int tid = threadIdx.x;

    const int ref_x = *p_refx;
    const int ref_y = *p_refy;

    int wx0 = ref_x - WSZ / 2; if (wx0 < 0) wx0 = 0;
    int wx1 = ref_x + WSZ / 2; if (wx1 > HDIM) wx1 = HDIM;
    int wy0 = ref_y - WSZ / 2; if (wy0 < 0) wy0 = 0;
    int wy1 = ref_y + WSZ / 2; if (wy1 > WDIM) wy1 = WDIM;

    const int Wh = wx1 - wx0;
    const int Ww = wy1 - wy0;
    const int Ph = Wh - PP + 1;
    const int Pw = Ww - PP + 1;
    const int M  = Ph * Pw;

    if (tid < NCHUNK) chunk_cnt[tid] = 0;

    const size_t base = (size_t)bc * HDIM * WDIM;

    // ---- Stage window into SMEM (coalesced rows) ----
    for (int t = tid; t < Wh * Ww; t += 256) {
        const int r = t / Ww;
        const int c = t - r * Ww;
        const size_t gidx = base + (size_t)(wx0 + r) * WDIM + (wy0 + c);
        wr[r][c] = g_re[gidx];
        wi[r][c] = g_im[gidx];
    }
    // Stage ref patch (contiguous, aligned) straight from GMEM.
    if (tid < PP * PP) {
        const int i = tid >> 3, j = tid & 7;
        const size_t gidx = base + (size_t)(ref_x + i) * WDIM + (ref_y + j);
        ref_r[tid] = g_re[gidx];
        ref_i[tid] = g_im[gidx];
    }
    __syncthreads();

    if (tid >= 32) {
        // ================= PRODUCERS (warps 1..7) =================
        const int p = tid - 32;
        for (int m = p; m < M; m += NPROD) {
            const int px = m / Pw;
            const int py = m - px * Pw;
            float s = 0.0f;
            #pragma unroll
            for (int i = 0; i < PP; i++) {
                const float4 r0 = *(const float4*)&ref_r[i * PP + 0];
                const float4 r1 = *(const float4*)&ref_r[i * PP + 4];
                const float4 m0 = *(const float4*)&ref_i[i * PP + 0];
                const float4 m1 = *(const float4*)&ref_i[i * PP + 4];
                const float rrow[8] = {r0.x, r0.y, r0.z, r0.w, r1.x, r1.y, r1.z, r1.w};
                const float irow[8] = {m0.x, m0.y, m0.z, m0.w, m1.x, m1.y, m1.z, m1.w};
                const float* wrow_r = &wr[px + i][py];
                const float* wrow_i = &wi[px + i][py];
                #pragma unroll
                for (int j = 0; j < PP; j++) {
                    const float dr = wrow_r[j] - rrow[j];
                    const float dm = wrow_i[j] - irow[j];
                    s += dr * dr;
                    s += dm * dm;
                }
            }
            dists[m] = s * (1.0f / 256.0f);   // 0.5 * mean over 128 elems
            __threadfence_block();
            atomicAdd(&chunk_cnt[m >> 5], 1);
        }
    } else {
        // ================= SCAN WARP (warp 0) =================
        const int lane = tid;
        float nd  = 1e33f;
        int   idx = -1;
        const volatile int* vcnt = chunk_cnt;
        for (int c0 = 0; c0 < M; c0 += 32) {
            const int cid = c0 >> 5;
            const int expected = (M - c0 < 32) ? (M - c0) : 32;
            while (vcnt[cid] < expected) { }     // wait for producers
            __threadfence_block();
            const float di = (lane < expected) ? dists[c0 + lane] : 3e38f;
            const float curmax = __shfl_sync(0xffffffffu, nd, 15);
            unsigned pass = __ballot_sync(0xffffffffu, di < curmax);
            while (pass) {
                const int j = __ffs(pass) - 1;   // ascending m: order matters
                pass &= pass - 1;
                const float dv = __shfl_sync(0xffffffffu, di, j);
                unsigned mask =
                    __ballot_sync(0xffffffffu, (lane < NSLOT) && (nd > dv)) & 0xffffu;
                if (mask) {
                    const int s = __ffs(mask) - 1;
                    if (lane == s) { nd = dv; idx = c0 + j; }
                }
            }
        }
        if (lane < NSLOT) sel[lane] = idx;
    }
    __syncthreads();

    // ---- Gather winning patches, write 2048 coalesced floats per CTA.
    // out layout: [bc][slot][k=i*8+j][comp], comp fastest.
    for (int t = tid; t < NSLOT * PP * PP * 2; t += 256) {
        const int comp = t & 1;
        const int k    = (t >> 1) & (PP * PP - 1);
        const int s    = t >> 7;
        const int m    = sel[s];
        float v = 0.0f;  // unfilled slot -> zeros (matches reference init)
        if (m >= 0) {
            const int px = m / Pw;
            const int py = m - px * Pw;
            const int i  = k >> 3;
            const int j  = k & 7;
            v = comp ? wi[px + i][py + j] : wr[px + i][py + j];
        }
        out[(size_t)bc * (NSLOT * PP * PP * 2) + t] = v;
    }
}

extern "C" void kernel_launch(void* const* d_in, const int* in_sizes, int n_in,
                              void* d_out, int out_size)
{
    const float* g_re = (const float*)d_in[0];
    const float* g_im = (const float*)d_in[1];
    const int*   refx = (const int*)d_in[2];
    const int*   refy = (const int*)d_in[3];
    float*       out  = (float*)d_out;

    const int BC = in_sizes[0] / (HDIM * WDIM);   // 96
    patches_kernel<<<BC, 256>>>(g_re, g_im, refx, refy, out);
}

// round 5
// speedup vs baseline: 2.9503x; 2.9503x over previous
#include <cuda_runtime.h>
#include <cuda_bf16.h>

// Problem constants (from reference): P=8, N=16, WS=32, H=W=512.
#define PP     8
#define NSLOT  16
#define WSZ    32
#define PITCH  36            // row pitch (multiple of 4 for float4 alignment)
#define HDIM   512
#define WDIM   512
#define MAXM   625           // (32-8+1)^2
#define NWARP  8

#define FINF __int_as_float(0x7f800000)

__global__ __launch_bounds__(256, 1)
void patches_kernel(const float* __restrict__ g_re,
                    const float* __restrict__ g_im,
                    const int*   __restrict__ p_refx,
                    const int*   __restrict__ p_refy,
                    float*       __restrict__ out)
{
    __shared__ float wr[WSZ][PITCH];
    __shared__ float wi[WSZ][PITCH];
    __shared__ float ref_r[PP * PP];   // contiguous, 16B-aligned ref patch
    __shared__ float ref_i[PP * PP];
    __shared__ float dists[MAXM];
    __shared__ float s_tot[NSLOT][NWARP];  // per-round per-warp scan totals
    __shared__ int   s_win[NSLOT][NWARP];  // per-round per-warp winner index
    __shared__ int   sel[NSLOT];

    const int bc   = blockIdx.x;
    const int tid  = threadIdx.x;
    const int lane = tid & 31;
    const int wrp  = tid >> 5;

    const int ref_x = *p_refx;
    const int ref_y = *p_refy;

    int wx0 = ref_x - WSZ / 2; if (wx0 < 0) wx0 = 0;
    int wx1 = ref_x + WSZ / 2; if (wx1 > HDIM) wx1 = HDIM;
    int wy0 = ref_y - WSZ / 2; if (wy0 < 0) wy0 = 0;
    int wy1 = ref_y + WSZ / 2; if (wy1 > WDIM) wy1 = WDIM;

    const int Wh = wx1 - wx0;
    const int Ww = wy1 - wy0;
    const int Ph = Wh - PP + 1;
    const int Pw = Ww - PP + 1;
    const int M  = Ph * Pw;

    const size_t base = (size_t)bc * HDIM * WDIM;

    // ---- Stage window into SMEM (coalesced rows) ----
    for (int t = tid; t < Wh * Ww; t += 256) {
        const int r = t / Ww;
        const int c = t - r * Ww;
        const size_t gidx = base + (size_t)(wx0 + r) * WDIM + (wy0 + c);
        wr[r][c] = g_re[gidx];
        wi[r][c] = g_im[gidx];
    }
    // Stage ref patch (contiguous) straight from GMEM.
    if (tid < PP * PP) {
        const int i = tid >> 3, j = tid & 7;
        const size_t gidx = base + (size_t)(ref_x + i) * WDIM + (ref_y + j);
        ref_r[tid] = g_re[gidx];
        ref_i[tid] = g_im[gidx];
    }
    __syncthreads();

    // ---- Distances: all 256 threads, strided patches. Accumulation order
    //      identical to reference (i, then j, re then im).
    for (int m = tid; m < M; m += 256) {
        const int px = m / Pw;
        const int py = m - px * Pw;
        float s = 0.0f;
        #pragma unroll
        for (int i = 0; i < PP; i++) {
            const float4 r0 = *(const float4*)&ref_r[i * PP + 0];
            const float4 r1 = *(const float4*)&ref_r[i * PP + 4];
            const float4 m0 = *(const float4*)&ref_i[i * PP + 0];
            const float4 m1 = *(const float4*)&ref_i[i * PP + 4];
            const float rrow[8] = {r0.x, r0.y, r0.z, r0.w, r1.x, r1.y, r1.z, r1.w};
            const float irow[8] = {m0.x, m0.y, m0.z, m0.w, m1.x, m1.y, m1.z, m1.w};
            const float* wrow_r = &wr[px + i][py];
            const float* wrow_i = &wi[px + i][py];
            #pragma unroll
            for (int j = 0; j < PP; j++) {
                const float dr = wrow_r[j] - rrow[j];
                const float dm = wrow_i[j] - irow[j];
                s += dr * dr;
                s += dm * dm;
            }
        }
        dists[m] = s * (1.0f / 256.0f);   // 0.5 * mean over 128 elems
    }
    __syncthreads();

    // ---- Parallel patience-sort selection: 16 rounds of exclusive
    //      prefix-min. Pile-j members = strict prefix-minima of the
    //      still-remaining subsequence; slot j's final content is the
    //      LAST pile-j member. Exact replay of reference semantics.
    const int m0 = 3 * tid, m1 = m0 + 1, m2 = m0 + 2;
    float d0 = (m0 < M) ? dists[m0] : FINF;
    float d1 = (m1 < M) ? dists[m1] : FINF;
    float d2 = (m2 < M) ? dists[m2] : FINF;
    bool  r0 = (m0 < M), r1 = (m1 < M), r2 = (m2 < M);

    #pragma unroll
    for (int j = 0; j < NSLOT; j++) {
        const float v0 = r0 ? d0 : FINF;
        const float v1 = r1 ? d1 : FINF;
        const float v2 = r2 ? d2 : FINF;
        float inc = fminf(fminf(v0, v1), v2);
        // inclusive warp scan (min)
        #pragma unroll
        for (int off = 1; off < 32; off <<= 1) {
            const float o = __shfl_up_sync(0xffffffffu, inc, off);
            if (lane >= off) inc = fminf(inc, o);
        }
        float excl = __shfl_up_sync(0xffffffffu, inc, 1);
        if (lane == 0) excl = FINF;
        if (lane == 31) s_tot[j][wrp] = inc;
        __syncthreads();
        float bmin = excl;
        for (int ww = 0; ww < wrp; ww++) bmin = fminf(bmin, s_tot[j][ww]);
        // exclusive prefix-min per element + membership
        const float pm1f = fminf(bmin, v0);
        const float pm2f = fminf(pm1f, v1);
        const bool mem0 = r0 && (d0 < bmin);
        const bool mem1 = r1 && (d1 < pm1f);
        const bool mem2 = r2 && (d2 < pm2f);
        r0 = r0 && !mem0;
        r1 = r1 && !mem1;
        r2 = r2 && !mem2;
        int widx = mem2 ? m2 : (mem1 ? m1 : (mem0 ? m0 : -1));
        #pragma unroll
        for (int off = 16; off; off >>= 1)
            widx = max(widx, __shfl_xor_sync(0xffffffffu, widx, off));
        if (lane == 0) s_win[j][wrp] = widx;
    }
    __syncthreads();
    if (tid < NSLOT) {
        int b = -1;
        #pragma unroll
        for (int ww = 0; ww < NWARP; ww++) b = max(b, s_win[tid][ww]);
        sel[tid] = b;
    }
    __syncthreads();

    // ---- Gather winning patches, write 2048 coalesced floats per CTA.
    // out layout: [bc][slot][k=i*8+j][comp], comp fastest.
    for (int t = tid; t < NSLOT * PP * PP * 2; t += 256) {
        const int comp = t & 1;
        const int k    = (t >> 1) & (PP * PP - 1);
        const int s    = t >> 7;
        const int m    = sel[s];
        float v = 0.0f;  // unfilled slot -> zeros (matches reference init)
        if (m >= 0) {
            const int px = m / Pw;
            const int py = m - px * Pw;
            const int i  = k >> 3;
            const int jj = k & 7;
            v = comp ? wi[px + i][py + jj] : wr[px + i][py + jj];
        }
        out[(size_t)bc * (NSLOT * PP * PP * 2) + t] = v;
    }
}

extern "C" void kernel_launch(void* const* d_in, const int* in_sizes, int n_in,
                              void* d_out, int out_size)
{
    const float* g_re = (const float*)d_in[0];
    const float* g_im = (const float*)d_in[1];
    const int*   refx = (const int*)d_in[2];
    const int*   refy = (const int*)d_in[3];
    float*       out  = (float*)d_out;

    const int BC = in_sizes[0] / (HDIM * WDIM);   // 96
    patches_kernel<<<BC, 256>>>(g_re, g_im, refx, refy, out);
}